// round 5
// baseline (speedup 1.0000x reference)
#include <cuda_runtime.h>
#include <cstdint>
#include <math.h>

#define BSZ 4
#define TLEN 2048
#define CDIM 1024
#define NH 16
#define HD 64
#define BT (BSZ * TLEN)      /* 8192 */
#define N3 (3 * CDIM)        /* 3072 */

// Scratch (allocation-free rule: __device__ globals)
__device__ float g_Q[BT * CDIM];      // [B,H,T,Dh]
__device__ float g_K[BT * CDIM];
__device__ float g_V[BT * CDIM];
__device__ float g_att[BT * CDIM];    // [B,T,C]
__device__ float g_WqkvT[N3 * CDIM];  // [3072,1024]  (W_qkv^T)
__device__ float g_WprojT[CDIM * CDIM];

// ---------------------------------------------------------------------------
// Portable tensor-core helpers (sm_80+ mma.sync — no 'a'-suffix features)
// ---------------------------------------------------------------------------
__device__ __forceinline__ uint32_t f2tf32(float x) {
    uint32_t u;
    asm("cvt.rna.tf32.f32 %0, %1;" : "=r"(u) : "f"(x));
    return u;
}

#define MMA_TF32(d, a, b)                                                        \
    asm volatile(                                                                \
        "mma.sync.aligned.m16n8k8.row.col.f32.tf32.tf32.f32 "                    \
        "{%0,%1,%2,%3}, {%4,%5,%6,%7}, {%8,%9}, {%0,%1,%2,%3};"                  \
        : "+f"((d)[0]), "+f"((d)[1]), "+f"((d)[2]), "+f"((d)[3])                 \
        : "r"((a)[0]), "r"((a)[1]), "r"((a)[2]), "r"((a)[3]),                    \
          "r"((b)[0]), "r"((b)[1]))

// ---------------------------------------------------------------------------
// One-shot weight transposes:  out[N,K] = in[K,N]^T
// ---------------------------------------------------------------------------
__global__ __launch_bounds__(256) void transpose32(const float* __restrict__ in,
                                                   float* __restrict__ out,
                                                   int R, int C) {
    __shared__ float tile[32][33];
    const int c0 = blockIdx.x * 32, r0 = blockIdx.y * 32;
    const int tx = threadIdx.x & 31, ty = threadIdx.x >> 5;
#pragma unroll
    for (int i = 0; i < 4; i++) {
        int r = ty + i * 8;
        tile[r][tx] = in[(size_t)(r0 + r) * C + c0 + tx];
    }
    __syncthreads();
#pragma unroll
    for (int i = 0; i < 4; i++) {
        int r = ty + i * 8;
        out[(size_t)(c0 + r) * R + r0 + tx] = tile[tx][r];
    }
}

// ---------------------------------------------------------------------------
// tf32 mma.sync GEMM (unchanged, passing)
// ---------------------------------------------------------------------------
#define SSTR 36

template <int MODE>
__global__ __launch_bounds__(256, 2)
void mm_tf32(const float* __restrict__ A, const float* __restrict__ Bt,
             const float* __restrict__ bias, float* __restrict__ out) {
    __shared__ uint32_t As[128 * SSTR];
    __shared__ uint32_t Bs[128 * SSTR];

    const int t = threadIdx.x;
    const int m0 = blockIdx.y * 128;
    const int n0 = blockIdx.x * 128;
    const int lane = t & 31, w = t >> 5;
    const int wr = w >> 2, wc = w & 3;

    float d[4][4][4];
#pragma unroll
    for (int i = 0; i < 4; i++)
#pragma unroll
        for (int j = 0; j < 4; j++)
#pragma unroll
            for (int e = 0; e < 4; e++) d[i][j][e] = 0.f;

    const int gr = t >> 3;
    const int gc4 = (t & 7) * 4;
    const float* Ap = A + (size_t)(m0 + gr) * CDIM + gc4;
    const float* Bp = Bt + (size_t)(n0 + gr) * CDIM + gc4;

    const int ar = wr * 64 + (lane >> 2);
    const int ac = lane & 3;
    const int br = wc * 32 + (lane >> 2);

    for (int k0 = 0; k0 < CDIM; k0 += 32) {
        __syncthreads();
#pragma unroll
        for (int p = 0; p < 4; p++) {
            const int row = gr + p * 32;
            float4 va = *(const float4*)(Ap + (size_t)(p * 32) * CDIM + k0);
            float4 vb = *(const float4*)(Bp + (size_t)(p * 32) * CDIM + k0);
            uint32_t* ad = &As[row * SSTR + gc4];
            uint32_t* bd = &Bs[row * SSTR + gc4];
            ad[0] = f2tf32(va.x); ad[1] = f2tf32(va.y);
            ad[2] = f2tf32(va.z); ad[3] = f2tf32(va.w);
            bd[0] = f2tf32(vb.x); bd[1] = f2tf32(vb.y);
            bd[2] = f2tf32(vb.z); bd[3] = f2tf32(vb.w);
        }
        __syncthreads();

#pragma unroll
        for (int ks = 0; ks < 4; ks++) {
            const int kk = ks * 8 + ac;
            uint32_t a[4][4], b[4][2];
#pragma unroll
            for (int i = 0; i < 4; i++) {
                const int r = (ar + i * 16) * SSTR;
                a[i][0] = As[r + kk];
                a[i][1] = As[r + 8 * SSTR + kk];
                a[i][2] = As[r + kk + 4];
                a[i][3] = As[r + 8 * SSTR + kk + 4];
            }
#pragma unroll
            for (int j = 0; j < 4; j++) {
                const int r = (br + j * 8) * SSTR;
                b[j][0] = Bs[r + kk];
                b[j][1] = Bs[r + kk + 4];
            }
#pragma unroll
            for (int i = 0; i < 4; i++)
#pragma unroll
                for (int j = 0; j < 4; j++) MMA_TF32(d[i][j], a[i], b[j]);
        }
    }

    const int r0 = lane >> 2, c0 = (lane & 3) * 2;
#pragma unroll
    for (int i = 0; i < 4; i++) {
        const int gmA = m0 + wr * 64 + i * 16 + r0;
        const int gmB = gmA + 8;
#pragma unroll
        for (int j = 0; j < 4; j++) {
            const int gn = n0 + wc * 32 + j * 8 + c0;
            const float bx = bias[gn], by = bias[gn + 1];
            float2 vA = make_float2(d[i][j][0] + bx, d[i][j][1] + by);
            float2 vB = make_float2(d[i][j][2] + bx, d[i][j][3] + by);
            if (MODE == 0) {
                const int which = gn >> 10;
                const int c = gn & 1023;
                const int h = c >> 6, d0 = c & 63;
                float* base = (which == 0) ? g_Q : ((which == 1) ? g_K : g_V);
                const int bA = gmA >> 11, tA = gmA & 2047;
                const int bB = gmB >> 11, tB = gmB & 2047;
                *(float2*)(base + ((size_t)(bA * NH + h) * TLEN + tA) * HD + d0) = vA;
                *(float2*)(base + ((size_t)(bB * NH + h) * TLEN + tB) * HD + d0) = vB;
            } else {
                *(float2*)(out + (size_t)gmA * CDIM + gn) = vA;
                *(float2*)(out + (size_t)gmB * CDIM + gn) = vB;
            }
        }
    }
}

// ---------------------------------------------------------------------------
// Tensor-core flash attention v2 (causal, tf32 mma.sync).
// Block = 256 threads (8 warps), Q tile 128, K tile 64. Warp w owns q rows
// [w*16, w*16+16). P never touches smem: C-frag -> A-frag via shfl permute.
// V stored transposed in smem (B operand is col-major).
// ---------------------------------------------------------------------------
#define SA 68
#define ATTN_SMEM ((128 + 64 + 64) * SA * 4)

__global__ __launch_bounds__(256) void attn_mma() {
    extern __shared__ uint32_t smw[];
    uint32_t* Qs = smw;                 // 128 x SA
    uint32_t* Ks = smw + 128 * SA;      // 64 x SA
    uint32_t* Vt = smw + 192 * SA;      // 64 x SA  (Vt[d][key])

    const int t = threadIdx.x;
    const int lane = t & 31, w = t >> 5;
    const int qi = (gridDim.x - 1) - blockIdx.x;  // heavy tiles first
    const int bh = blockIdx.y;
    const int q0 = qi * 128;

    const float* Qg = g_Q + (size_t)bh * TLEN * HD;
    const float* Kg = g_K + (size_t)bh * TLEN * HD;
    const float* Vg = g_V + (size_t)bh * TLEN * HD;

    // Stage Q tile once, scale folded in (1/sqrt(64) = 0.125)
#pragma unroll
    for (int it = 0; it < 8; it++) {
        const int i = it * 256 + t;
        const int row = i >> 4, c4 = (i & 15) * 4;
        float4 v = *(const float4*)(Qg + (size_t)(q0 + row) * HD + c4);
        uint4 u;
        u.x = f2tf32(v.x * 0.125f);
        u.y = f2tf32(v.y * 0.125f);
        u.z = f2tf32(v.z * 0.125f);
        u.w = f2tf32(v.w * 0.125f);
        *(uint4*)&Qs[row * SA + c4] = u;
    }

    const int r0w = w * 16 + (lane >> 2);   // warp q row (first of pair)
    const int abase = r0w * SA;
    const int lk = lane & 3;
    // shfl sources for C-frag -> A-frag permute
    const int src0 = (lane & 28) + ((lane >> 1) & 1);
    const int src1 = src0 + 2;
    const bool oddl = lane & 1;

    float o[8][4];
#pragma unroll
    for (int j = 0; j < 8; j++)
#pragma unroll
        for (int e = 0; e < 4; e++) o[j][e] = 0.f;
    float m0 = -1e30f, m1 = -1e30f, l0 = 0.f, l1 = 0.f;

    const int nkt = 2 * qi + 2;
    for (int kt = 0; kt < nkt; kt++) {
        const int k0 = kt * 64;
        __syncthreads();  // Ks/Vt free of prior readers (also covers Q store)
#pragma unroll
        for (int it = 0; it < 4; it++) {
            const int i = it * 256 + t;
            const int row = i >> 4, c4 = (i & 15) * 4;
            float4 kv = *(const float4*)(Kg + (size_t)(k0 + row) * HD + c4);
            uint4 u;
            u.x = f2tf32(kv.x); u.y = f2tf32(kv.y);
            u.z = f2tf32(kv.z); u.w = f2tf32(kv.w);
            *(uint4*)&Ks[row * SA + c4] = u;
            float4 vv = *(const float4*)(Vg + (size_t)(k0 + row) * HD + c4);
            Vt[(c4 + 0) * SA + row] = f2tf32(vv.x);
            Vt[(c4 + 1) * SA + row] = f2tf32(vv.y);
            Vt[(c4 + 2) * SA + row] = f2tf32(vv.z);
            Vt[(c4 + 3) * SA + row] = f2tf32(vv.w);
        }
        __syncthreads();

        // Fully masked half-tile for warps 0-3: skip compute (no syncs inside)
        if (kt == 2 * qi + 1 && w < 4) continue;

        // S = (Q*scale) @ K^T
        float s[8][4];
#pragma unroll
        for (int j = 0; j < 8; j++)
#pragma unroll
            for (int e = 0; e < 4; e++) s[j][e] = 0.f;
#pragma unroll
        for (int ks = 0; ks < 8; ks++) {
            const int kk = ks * 8 + lk;
            uint32_t a[4];
            a[0] = Qs[abase + kk];
            a[1] = Qs[abase + 8 * SA + kk];
            a[2] = Qs[abase + kk + 4];
            a[3] = Qs[abase + 8 * SA + kk + 4];
#pragma unroll
            for (int j = 0; j < 8; j++) {
                const int r = (j * 8 + (lane >> 2)) * SA;
                uint32_t b[2];
                b[0] = Ks[r + kk];
                b[1] = Ks[r + kk + 4];
                MMA_TF32(s[j], a, b);
            }
        }

        // Causal mask (diagonal region only; uniform branch)
        if (kt >= 2 * qi) {
            const int gr0 = q0 + r0w, gr1 = gr0 + 8;
#pragma unroll
            for (int j = 0; j < 8; j++) {
                const int c = k0 + j * 8 + 2 * lk;
                if (c > gr0) s[j][0] = -1e30f;
                if (c + 1 > gr0) s[j][1] = -1e30f;
                if (c > gr1) s[j][2] = -1e30f;
                if (c + 1 > gr1) s[j][3] = -1e30f;
            }
        }

        // Online softmax: rows r0w (c0,c1) and r0w+8 (c2,c3)
        float tm0 = -1e30f, tm1 = -1e30f;
#pragma unroll
        for (int j = 0; j < 8; j++) {
            tm0 = fmaxf(tm0, fmaxf(s[j][0], s[j][1]));
            tm1 = fmaxf(tm1, fmaxf(s[j][2], s[j][3]));
        }
        tm0 = fmaxf(tm0, __shfl_xor_sync(0xffffffffu, tm0, 1));
        tm0 = fmaxf(tm0, __shfl_xor_sync(0xffffffffu, tm0, 2));
        tm1 = fmaxf(tm1, __shfl_xor_sync(0xffffffffu, tm1, 1));
        tm1 = fmaxf(tm1, __shfl_xor_sync(0xffffffffu, tm1, 2));

        const float mn0 = fmaxf(m0, tm0), mn1 = fmaxf(m1, tm1);
        const float al0 = __expf(m0 - mn0), al1 = __expf(m1 - mn1);
        m0 = mn0; m1 = mn1;

        float rs0 = 0.f, rs1 = 0.f;
#pragma unroll
        for (int j = 0; j < 8; j++) {
            s[j][0] = __expf(s[j][0] - mn0); rs0 += s[j][0];
            s[j][1] = __expf(s[j][1] - mn0); rs0 += s[j][1];
            s[j][2] = __expf(s[j][2] - mn1); rs1 += s[j][2];
            s[j][3] = __expf(s[j][3] - mn1); rs1 += s[j][3];
        }
        rs0 += __shfl_xor_sync(0xffffffffu, rs0, 1);
        rs0 += __shfl_xor_sync(0xffffffffu, rs0, 2);
        rs1 += __shfl_xor_sync(0xffffffffu, rs1, 1);
        rs1 += __shfl_xor_sync(0xffffffffu, rs1, 2);
        l0 = l0 * al0 + rs0;
        l1 = l1 * al1 + rs1;
#pragma unroll
        for (int j = 0; j < 8; j++) {
            o[j][0] *= al0; o[j][1] *= al0;
            o[j][2] *= al1; o[j][3] *= al1;
        }

        // O += P @ V. P A-frags built from s C-frags by in-register permute:
        // element (r,c): C owner lane 4r+(c>>1) slot c&1 -> A owner lane 4r+(c&3).
#pragma unroll
        for (int ks = 0; ks < 8; ks++) {
            float v00 = __shfl_sync(0xffffffffu, s[ks][0], src0);
            float v01 = __shfl_sync(0xffffffffu, s[ks][1], src0);
            float v20 = __shfl_sync(0xffffffffu, s[ks][2], src0);
            float v21 = __shfl_sync(0xffffffffu, s[ks][3], src0);
            float v0b = __shfl_sync(0xffffffffu, s[ks][0], src1);
            float v1b = __shfl_sync(0xffffffffu, s[ks][1], src1);
            float v2b = __shfl_sync(0xffffffffu, s[ks][2], src1);
            float v3b = __shfl_sync(0xffffffffu, s[ks][3], src1);
            uint32_t a[4];
            a[0] = f2tf32(oddl ? v01 : v00);
            a[1] = f2tf32(oddl ? v21 : v20);
            a[2] = f2tf32(oddl ? v1b : v0b);
            a[3] = f2tf32(oddl ? v3b : v2b);
            const int kk = ks * 8 + lk;
#pragma unroll
            for (int j = 0; j < 8; j++) {
                const int r = (j * 8 + (lane >> 2)) * SA;
                uint32_t b[2];
                b[0] = Vt[r + kk];
                b[1] = Vt[r + kk + 4];
                MMA_TF32(o[j], a, b);
            }
        }
    }

    // Epilogue -> g_att [B,T,C]
    const float inv0 = 1.f / l0, inv1 = 1.f / l1;
    const int b = bh >> 4, h = bh & 15;
    const int gr0 = q0 + r0w, gr1 = gr0 + 8;
    float* o0 = g_att + ((size_t)(b * TLEN + gr0)) * CDIM + h * HD;
    float* o1 = g_att + ((size_t)(b * TLEN + gr1)) * CDIM + h * HD;
#pragma unroll
    for (int j = 0; j < 8; j++) {
        const int c = j * 8 + 2 * lk;
        *(float2*)(o0 + c) = make_float2(o[j][0] * inv0, o[j][1] * inv0);
        *(float2*)(o1 + c) = make_float2(o[j][2] * inv1, o[j][3] * inv1);
    }
}

// ---------------------------------------------------------------------------
extern "C" void kernel_launch(void* const* d_in, const int* in_sizes, int n_in,
                              void* d_out, int out_size) {
    const float* x = (const float*)d_in[0];
    const float* W_qkv = (const float*)d_in[1];
    const float* b_qkv = (const float*)d_in[2];
    const float* W_proj = (const float*)d_in[3];
    const float* b_proj = (const float*)d_in[4];
    float* out = (float*)d_out;

    float *wqkvT = nullptr, *wprojT = nullptr, *attp = nullptr;
    cudaGetSymbolAddress((void**)&wqkvT, g_WqkvT);
    cudaGetSymbolAddress((void**)&wprojT, g_WprojT);
    cudaGetSymbolAddress((void**)&attp, g_att);

    cudaFuncSetAttribute(attn_mma, cudaFuncAttributeMaxDynamicSharedMemorySize,
                         ATTN_SMEM);

    transpose32<<<dim3(N3 / 32, CDIM / 32), 256>>>(W_qkv, wqkvT, CDIM, N3);
    transpose32<<<dim3(CDIM / 32, CDIM / 32), 256>>>(W_proj, wprojT, CDIM, CDIM);

    mm_tf32<0><<<dim3(N3 / 128, BT / 128), 256>>>(x, wqkvT, b_qkv, nullptr);

    attn_mma<<<dim3(TLEN / 128, BSZ * NH), 256, ATTN_SMEM>>>();

    mm_tf32<1><<<dim3(CDIM / 128, BT / 128), 256>>>(attp, wprojT, b_proj, out);
}

// round 6
// speedup vs baseline: 1.4979x; 1.4979x over previous
#include <cuda_runtime.h>
#include <cstdint>
#include <math.h>

#define BSZ 4
#define TLEN 2048
#define CDIM 1024
#define NH 16
#define HD 64
#define BT (BSZ * TLEN)      /* 8192 */
#define N3 (3 * CDIM)        /* 3072 */

// Scratch (allocation-free rule: __device__ globals)
__device__ float g_Q[BT * CDIM];      // [B,H,T,Dh]
__device__ float g_K[BT * CDIM];
__device__ float g_V[BT * CDIM];
__device__ float g_att[BT * CDIM];    // [B,T,C]
__device__ float g_WqkvT[N3 * CDIM];  // [3072,1024]  (W_qkv^T)
__device__ float g_WprojT[CDIM * CDIM];

// ---------------------------------------------------------------------------
// Portable tensor-core helpers (sm_80+ mma.sync — no 'a'-suffix features)
// ---------------------------------------------------------------------------
__device__ __forceinline__ uint32_t f2tf32(float x) {
    uint32_t u;
    asm("cvt.rna.tf32.f32 %0, %1;" : "=r"(u) : "f"(x));
    return u;
}

#define MMA_TF32(d, a, b)                                                        \
    asm volatile(                                                                \
        "mma.sync.aligned.m16n8k8.row.col.f32.tf32.tf32.f32 "                    \
        "{%0,%1,%2,%3}, {%4,%5,%6,%7}, {%8,%9}, {%0,%1,%2,%3};"                  \
        : "+f"((d)[0]), "+f"((d)[1]), "+f"((d)[2]), "+f"((d)[3])                 \
        : "r"((a)[0]), "r"((a)[1]), "r"((a)[2]), "r"((a)[3]),                    \
          "r"((b)[0]), "r"((b)[1]))

// ---------------------------------------------------------------------------
// One-shot weight transposes:  out[N,K] = in[K,N]^T
// ---------------------------------------------------------------------------
__global__ __launch_bounds__(256) void transpose32(const float* __restrict__ in,
                                                   float* __restrict__ out,
                                                   int R, int C) {
    __shared__ float tile[32][33];
    const int c0 = blockIdx.x * 32, r0 = blockIdx.y * 32;
    const int tx = threadIdx.x & 31, ty = threadIdx.x >> 5;
#pragma unroll
    for (int i = 0; i < 4; i++) {
        int r = ty + i * 8;
        tile[r][tx] = in[(size_t)(r0 + r) * C + c0 + tx];
    }
    __syncthreads();
#pragma unroll
    for (int i = 0; i < 4; i++) {
        int r = ty + i * 8;
        out[(size_t)(c0 + r) * R + r0 + tx] = tile[tx][r];
    }
}

// ---------------------------------------------------------------------------
// tf32 mma.sync GEMM (unchanged, passing)
// ---------------------------------------------------------------------------
#define SSTR 36

template <int MODE>
__global__ __launch_bounds__(256, 2)
void mm_tf32(const float* __restrict__ A, const float* __restrict__ Bt,
             const float* __restrict__ bias, float* __restrict__ out) {
    __shared__ uint32_t As[128 * SSTR];
    __shared__ uint32_t Bs[128 * SSTR];

    const int t = threadIdx.x;
    const int m0 = blockIdx.y * 128;
    const int n0 = blockIdx.x * 128;
    const int lane = t & 31, w = t >> 5;
    const int wr = w >> 2, wc = w & 3;

    float d[4][4][4];
#pragma unroll
    for (int i = 0; i < 4; i++)
#pragma unroll
        for (int j = 0; j < 4; j++)
#pragma unroll
            for (int e = 0; e < 4; e++) d[i][j][e] = 0.f;

    const int gr = t >> 3;
    const int gc4 = (t & 7) * 4;
    const float* Ap = A + (size_t)(m0 + gr) * CDIM + gc4;
    const float* Bp = Bt + (size_t)(n0 + gr) * CDIM + gc4;

    const int ar = wr * 64 + (lane >> 2);
    const int ac = lane & 3;
    const int br = wc * 32 + (lane >> 2);

    for (int k0 = 0; k0 < CDIM; k0 += 32) {
        __syncthreads();
#pragma unroll
        for (int p = 0; p < 4; p++) {
            const int row = gr + p * 32;
            float4 va = *(const float4*)(Ap + (size_t)(p * 32) * CDIM + k0);
            float4 vb = *(const float4*)(Bp + (size_t)(p * 32) * CDIM + k0);
            uint32_t* ad = &As[row * SSTR + gc4];
            uint32_t* bd = &Bs[row * SSTR + gc4];
            ad[0] = f2tf32(va.x); ad[1] = f2tf32(va.y);
            ad[2] = f2tf32(va.z); ad[3] = f2tf32(va.w);
            bd[0] = f2tf32(vb.x); bd[1] = f2tf32(vb.y);
            bd[2] = f2tf32(vb.z); bd[3] = f2tf32(vb.w);
        }
        __syncthreads();

#pragma unroll
        for (int ks = 0; ks < 4; ks++) {
            const int kk = ks * 8 + ac;
            uint32_t a[4][4], b[4][2];
#pragma unroll
            for (int i = 0; i < 4; i++) {
                const int r = (ar + i * 16) * SSTR;
                a[i][0] = As[r + kk];
                a[i][1] = As[r + 8 * SSTR + kk];
                a[i][2] = As[r + kk + 4];
                a[i][3] = As[r + 8 * SSTR + kk + 4];
            }
#pragma unroll
            for (int j = 0; j < 4; j++) {
                const int r = (br + j * 8) * SSTR;
                b[j][0] = Bs[r + kk];
                b[j][1] = Bs[r + kk + 4];
            }
#pragma unroll
            for (int i = 0; i < 4; i++)
#pragma unroll
                for (int j = 0; j < 4; j++) MMA_TF32(d[i][j], a[i], b[j]);
        }
    }

    const int r0 = lane >> 2, c0 = (lane & 3) * 2;
#pragma unroll
    for (int i = 0; i < 4; i++) {
        const int gmA = m0 + wr * 64 + i * 16 + r0;
        const int gmB = gmA + 8;
#pragma unroll
        for (int j = 0; j < 4; j++) {
            const int gn = n0 + wc * 32 + j * 8 + c0;
            const float bx = bias[gn], by = bias[gn + 1];
            float2 vA = make_float2(d[i][j][0] + bx, d[i][j][1] + by);
            float2 vB = make_float2(d[i][j][2] + bx, d[i][j][3] + by);
            if (MODE == 0) {
                const int which = gn >> 10;
                const int c = gn & 1023;
                const int h = c >> 6, d0 = c & 63;
                float* base = (which == 0) ? g_Q : ((which == 1) ? g_K : g_V);
                const int bA = gmA >> 11, tA = gmA & 2047;
                const int bB = gmB >> 11, tB = gmB & 2047;
                *(float2*)(base + ((size_t)(bA * NH + h) * TLEN + tA) * HD + d0) = vA;
                *(float2*)(base + ((size_t)(bB * NH + h) * TLEN + tB) * HD + d0) = vB;
            } else {
                *(float2*)(out + (size_t)gmA * CDIM + gn) = vA;
                *(float2*)(out + (size_t)gmB * CDIM + gn) = vB;
            }
        }
    }
}

// ---------------------------------------------------------------------------
// Tensor-core flash attention v3 (causal, tf32 mma.sync).
// Block = 128 threads (4 warps), Q tile 64, K tile 64; grid 2048, heavy-first.
// Q fragments live in registers (loaded once via the K buffer). P transposed
// C-frag -> A-frag by shfl (no smem, no extra barrier): 2 barriers / tile.
// V stored transposed in smem (B operand is col-major).
// ---------------------------------------------------------------------------
#define SA 68
#define ATTN_SMEM (2 * 64 * SA * 4)

__global__ __launch_bounds__(128) void attn_mma() {
    extern __shared__ uint32_t smw[];
    uint32_t* Ks = smw;               // 64 x SA (also Q staging pre-loop)
    uint32_t* Vt = smw + 64 * SA;     // 64 x SA  (Vt[d][key])

    const int t = threadIdx.x;
    const int lane = t & 31, w = t >> 5;
    const int qi = (gridDim.x - 1) - blockIdx.x;  // heavy tiles first
    const int bh = blockIdx.y;
    const int q0 = qi * 64;

    const float* Qg = g_Q + (size_t)bh * TLEN * HD;
    const float* Kg = g_K + (size_t)bh * TLEN * HD;
    const float* Vg = g_V + (size_t)bh * TLEN * HD;

    const int r0w = w * 16 + (lane >> 2);   // warp q row (first of pair)
    const int abase = r0w * SA;
    const int lk = lane & 3;
    // shfl sources for C-frag -> A-frag permute
    const int src0 = (lane & 28) + ((lane >> 1) & 1);
    const int src1 = src0 + 2;
    const bool oddl = lane & 1;

    // Stage Q through the K buffer, then hoist fragments to registers.
    for (int i = t; i < 64 * 16; i += 128) {
        const int row = i >> 4, c4 = (i & 15) * 4;
        float4 v = *(const float4*)(Qg + (size_t)(q0 + row) * HD + c4);
        uint4 u;
        u.x = f2tf32(v.x * 0.125f);
        u.y = f2tf32(v.y * 0.125f);
        u.z = f2tf32(v.z * 0.125f);
        u.w = f2tf32(v.w * 0.125f);
        *(uint4*)&Ks[row * SA + c4] = u;
    }
    __syncthreads();
    uint32_t qf[8][4];
#pragma unroll
    for (int ks = 0; ks < 8; ks++) {
        const int kk = ks * 8 + lk;
        qf[ks][0] = Ks[abase + kk];
        qf[ks][1] = Ks[abase + 8 * SA + kk];
        qf[ks][2] = Ks[abase + kk + 4];
        qf[ks][3] = Ks[abase + 8 * SA + kk + 4];
    }

    float o[8][4];
#pragma unroll
    for (int j = 0; j < 8; j++)
#pragma unroll
        for (int e = 0; e < 4; e++) o[j][e] = 0.f;
    float m0 = -1e30f, m1 = -1e30f, l0 = 0.f, l1 = 0.f;

    for (int kt = 0; kt <= qi; kt++) {
        const int k0 = kt * 64;
        __syncthreads();  // Ks free of prior readers (incl. Q frag loads)
        for (int i = t; i < 64 * 16; i += 128) {
            const int row = i >> 4, c4 = (i & 15) * 4;
            float4 kv = *(const float4*)(Kg + (size_t)(k0 + row) * HD + c4);
            uint4 u;
            u.x = f2tf32(kv.x); u.y = f2tf32(kv.y);
            u.z = f2tf32(kv.z); u.w = f2tf32(kv.w);
            *(uint4*)&Ks[row * SA + c4] = u;
            float4 vv = *(const float4*)(Vg + (size_t)(k0 + row) * HD + c4);
            Vt[(c4 + 0) * SA + row] = f2tf32(vv.x);
            Vt[(c4 + 1) * SA + row] = f2tf32(vv.y);
            Vt[(c4 + 2) * SA + row] = f2tf32(vv.z);
            Vt[(c4 + 3) * SA + row] = f2tf32(vv.w);
        }
        __syncthreads();

        // S = (Q*scale) @ K^T   (Q from registers)
        float s[8][4];
#pragma unroll
        for (int j = 0; j < 8; j++)
#pragma unroll
            for (int e = 0; e < 4; e++) s[j][e] = 0.f;
#pragma unroll
        for (int ks = 0; ks < 8; ks++) {
            const int kk = ks * 8 + lk;
#pragma unroll
            for (int j = 0; j < 8; j++) {
                const int r = (j * 8 + (lane >> 2)) * SA;
                uint32_t b[2];
                b[0] = Ks[r + kk];
                b[1] = Ks[r + kk + 4];
                MMA_TF32(s[j], qf[ks], b);
            }
        }

        // Causal mask (diagonal tile only; uniform branch)
        if (kt == qi) {
            const int gr0 = q0 + r0w, gr1 = gr0 + 8;
#pragma unroll
            for (int j = 0; j < 8; j++) {
                const int c = k0 + j * 8 + 2 * lk;
                if (c > gr0) s[j][0] = -1e30f;
                if (c + 1 > gr0) s[j][1] = -1e30f;
                if (c > gr1) s[j][2] = -1e30f;
                if (c + 1 > gr1) s[j][3] = -1e30f;
            }
        }

        // Online softmax: rows r0w (c0,c1) and r0w+8 (c2,c3)
        float tm0 = -1e30f, tm1 = -1e30f;
#pragma unroll
        for (int j = 0; j < 8; j++) {
            tm0 = fmaxf(tm0, fmaxf(s[j][0], s[j][1]));
            tm1 = fmaxf(tm1, fmaxf(s[j][2], s[j][3]));
        }
        tm0 = fmaxf(tm0, __shfl_xor_sync(0xffffffffu, tm0, 1));
        tm0 = fmaxf(tm0, __shfl_xor_sync(0xffffffffu, tm0, 2));
        tm1 = fmaxf(tm1, __shfl_xor_sync(0xffffffffu, tm1, 1));
        tm1 = fmaxf(tm1, __shfl_xor_sync(0xffffffffu, tm1, 2));

        const float mn0 = fmaxf(m0, tm0), mn1 = fmaxf(m1, tm1);
        const float al0 = __expf(m0 - mn0), al1 = __expf(m1 - mn1);
        m0 = mn0; m1 = mn1;

        float rs0 = 0.f, rs1 = 0.f;
#pragma unroll
        for (int j = 0; j < 8; j++) {
            s[j][0] = __expf(s[j][0] - mn0); rs0 += s[j][0];
            s[j][1] = __expf(s[j][1] - mn0); rs0 += s[j][1];
            s[j][2] = __expf(s[j][2] - mn1); rs1 += s[j][2];
            s[j][3] = __expf(s[j][3] - mn1); rs1 += s[j][3];
        }
        rs0 += __shfl_xor_sync(0xffffffffu, rs0, 1);
        rs0 += __shfl_xor_sync(0xffffffffu, rs0, 2);
        rs1 += __shfl_xor_sync(0xffffffffu, rs1, 1);
        rs1 += __shfl_xor_sync(0xffffffffu, rs1, 2);
        l0 = l0 * al0 + rs0;
        l1 = l1 * al1 + rs1;
#pragma unroll
        for (int j = 0; j < 8; j++) {
            o[j][0] *= al0; o[j][1] *= al0;
            o[j][2] *= al1; o[j][3] *= al1;
        }

        // O += P @ V. P A-frags from s C-frags via in-register permute:
        // element (r,c): C owner lane 4r+(c>>1) slot c&1 -> A owner lane 4r+(c&3).
#pragma unroll
        for (int ks = 0; ks < 8; ks++) {
            float v00 = __shfl_sync(0xffffffffu, s[ks][0], src0);
            float v01 = __shfl_sync(0xffffffffu, s[ks][1], src0);
            float v20 = __shfl_sync(0xffffffffu, s[ks][2], src0);
            float v21 = __shfl_sync(0xffffffffu, s[ks][3], src0);
            float v0b = __shfl_sync(0xffffffffu, s[ks][0], src1);
            float v1b = __shfl_sync(0xffffffffu, s[ks][1], src1);
            float v2b = __shfl_sync(0xffffffffu, s[ks][2], src1);
            float v3b = __shfl_sync(0xffffffffu, s[ks][3], src1);
            uint32_t a[4];
            a[0] = f2tf32(oddl ? v01 : v00);
            a[1] = f2tf32(oddl ? v21 : v20);
            a[2] = f2tf32(oddl ? v1b : v0b);
            a[3] = f2tf32(oddl ? v3b : v2b);
            const int kk = ks * 8 + lk;
#pragma unroll
            for (int j = 0; j < 8; j++) {
                const int r = (j * 8 + (lane >> 2)) * SA;
                uint32_t b[2];
                b[0] = Vt[r + kk];
                b[1] = Vt[r + kk + 4];
                MMA_TF32(o[j], a, b);
            }
        }
    }

    // Epilogue -> g_att [B,T,C]
    const float inv0 = 1.f / l0, inv1 = 1.f / l1;
    const int b = bh >> 4, h = bh & 15;
    const int gr0 = q0 + r0w, gr1 = gr0 + 8;
    float* o0 = g_att + ((size_t)(b * TLEN + gr0)) * CDIM + h * HD;
    float* o1 = g_att + ((size_t)(b * TLEN + gr1)) * CDIM + h * HD;
#pragma unroll
    for (int j = 0; j < 8; j++) {
        const int c = j * 8 + 2 * lk;
        *(float2*)(o0 + c) = make_float2(o[j][0] * inv0, o[j][1] * inv0);
        *(float2*)(o1 + c) = make_float2(o[j][2] * inv1, o[j][3] * inv1);
    }
}

// ---------------------------------------------------------------------------
extern "C" void kernel_launch(void* const* d_in, const int* in_sizes, int n_in,
                              void* d_out, int out_size) {
    const float* x = (const float*)d_in[0];
    const float* W_qkv = (const float*)d_in[1];
    const float* b_qkv = (const float*)d_in[2];
    const float* W_proj = (const float*)d_in[3];
    const float* b_proj = (const float*)d_in[4];
    float* out = (float*)d_out;

    float *wqkvT = nullptr, *wprojT = nullptr, *attp = nullptr;
    cudaGetSymbolAddress((void**)&wqkvT, g_WqkvT);
    cudaGetSymbolAddress((void**)&wprojT, g_WprojT);
    cudaGetSymbolAddress((void**)&attp, g_att);

    cudaFuncSetAttribute(attn_mma, cudaFuncAttributeMaxDynamicSharedMemorySize,
                         ATTN_SMEM);

    transpose32<<<dim3(N3 / 32, CDIM / 32), 256>>>(W_qkv, wqkvT, CDIM, N3);
    transpose32<<<dim3(CDIM / 32, CDIM / 32), 256>>>(W_proj, wprojT, CDIM, CDIM);

    mm_tf32<0><<<dim3(N3 / 128, BT / 128), 256>>>(x, wqkvT, b_qkv, nullptr);

    attn_mma<<<dim3(TLEN / 64, BSZ * NH), 128, ATTN_SMEM>>>();

    mm_tf32<1><<<dim3(CDIM / 128, BT / 128), 256>>>(attp, wprojT, b_proj, out);
}